// round 14
// baseline (speedup 1.0000x reference)
#include <cuda_runtime.h>
#include <cuda_bf16.h>
#include <stdint.h>
#include <math.h>

#define Bb 4
#define Ss 2048
#define Hh 768
#define NH 12
#define HD 64

// ---------------------------------------------------------------------------
// Scratch (allocation-free rule: __device__ globals) — bf16 hi/lo planes
// ---------------------------------------------------------------------------
__device__ __nv_bfloat16 g_xh[Bb * Ss * Hh],  g_xl[Bb * Ss * Hh];
__device__ __nv_bfloat16 g_wqh[Hh * 3 * Hh],  g_wql[Hh * 3 * Hh];
__device__ __nv_bfloat16 g_woh[Hh * Hh],      g_wol[Hh * Hh];
__device__ __nv_bfloat16 g_qkvh[3 * Bb * NH * Ss * HD], g_qkvl[3 * Bb * NH * Ss * HD];
__device__ __nv_bfloat16 g_ctxh[Bb * Ss * Hh], g_ctxl[Bb * Ss * Hh];

#define SCL 0.18033688011112042f   // 0.125 * log2(e), folded into Q at QKV epilogue

// ---------------------------------------------------------------------------
// Helpers
// ---------------------------------------------------------------------------
__device__ __forceinline__ uint32_t packbf(float lo, float hi) {
    uint32_t r;
    asm("cvt.rn.bf16x2.f32 %0, %1, %2;" : "=r"(r) : "f"(hi), "f"(lo));
    return r;
}
__device__ __forceinline__ float2 unpackbf(uint32_t u) {
    __nv_bfloat162 h = *reinterpret_cast<__nv_bfloat162*>(&u);
    return make_float2(__bfloat162float(h.x), __bfloat162float(h.y));
}
__device__ __forceinline__ void split2(float x, float y, uint32_t& hi, uint32_t& lo) {
    hi = packbf(x, y);
    float2 h = unpackbf(hi);
    lo = packbf(x - h.x, y - h.y);
}

#define LDSM4(r0, r1, r2, r3, a)                                              \
    asm volatile("ldmatrix.sync.aligned.m8n8.x4.shared.b16 {%0,%1,%2,%3}, [%4];" \
                 : "=r"(r0), "=r"(r1), "=r"(r2), "=r"(r3) : "r"(a))
#define LDSM4T(r0, r1, r2, r3, a)                                             \
    asm volatile("ldmatrix.sync.aligned.m8n8.x4.trans.shared.b16 {%0,%1,%2,%3}, [%4];" \
                 : "=r"(r0), "=r"(r1), "=r"(r2), "=r"(r3) : "r"(a))
#define CPA(dst, src)                                                         \
    asm volatile("cp.async.cg.shared.global [%0], [%1], 16;" :: "r"(dst), "l"(src))
#define CPCOMMIT() asm volatile("cp.async.commit_group;")
#define CPWAIT0()  asm volatile("cp.async.wait_group 0;")
#define CPWAIT1()  asm volatile("cp.async.wait_group 1;")

__device__ __forceinline__ void mma16816(float* c, const uint32_t* a,
                                         uint32_t b0, uint32_t b1) {
    asm volatile(
        "mma.sync.aligned.m16n8k16.row.col.f32.bf16.bf16.f32 "
        "{%0,%1,%2,%3}, {%4,%5,%6,%7}, {%8,%9}, {%0,%1,%2,%3};"
        : "+f"(c[0]), "+f"(c[1]), "+f"(c[2]), "+f"(c[3])
        : "r"(a[0]), "r"(a[1]), "r"(a[2]), "r"(a[3]), "r"(b0), "r"(b1));
}
__device__ __forceinline__ uint32_t sptr(const void* p) {
    return (uint32_t)__cvta_generic_to_shared(p);
}

// ---------------------------------------------------------------------------
// fp32 -> bf16 hi/lo convert prepass (separate launches — R12 baseline)
// ---------------------------------------------------------------------------
__global__ void cvt_kernel(const float* __restrict__ in,
                           __nv_bfloat16* __restrict__ hi,
                           __nv_bfloat16* __restrict__ lo, int n)
{
    int i = (blockIdx.x * blockDim.x + threadIdx.x) * 4;
    if (i < n) {
        float4 v = *(const float4*)(in + i);
        uint32_t h0, l0, h1, l1;
        split2(v.x, v.y, h0, l0);
        split2(v.z, v.w, h1, l1);
        uint32_t* ph = (uint32_t*)(hi + i);
        uint32_t* pl = (uint32_t*)(lo + i);
        ph[0] = h0; ph[1] = h1;
        pl[0] = l0; pl[1] = l1;
    }
}

// ---------------------------------------------------------------------------
// Projection GEMM, bf16x3 (hh + lh + hl), 128 x NCOLS CTA tile, BK=32,
// 4 warps of 64 x (NCOLS/2), 3-stage cp.async, single barrier per k-chunk.
// MODE 1 (NCOLS=128): scatter epilogue -> g_qkvh/l (Q scaled by SCL).
// MODE 2: fp32 C. NCOLS=64 halves task size for tail-free out-proj.
// ---------------------------------------------------------------------------
#define ASTR 40

template <int MODE, int NCOLS>
__global__ void __launch_bounds__(128, 2)
gemm_bf(const __nv_bfloat16* __restrict__ Ah, const __nv_bfloat16* __restrict__ Al,
        const __nv_bfloat16* __restrict__ Bh, const __nv_bfloat16* __restrict__ Bl,
        float* __restrict__ C, int M, int N, int K)
{
    constexpr int BSTRX = (NCOLS == 128) ? 136 : 72;
    constexpr int NF = NCOLS / 16;                   // n-fragments per warp
    constexpr int STG = 2 * 128 * ASTR + 2 * 32 * BSTRX;
    constexpr int CSH = (NCOLS == 128) ? 4 : 3;      // log2(NCOLS/8) B-loader shift
    extern __shared__ __align__(16) __nv_bfloat16 smg[];

    const int t = threadIdx.x;
    const int lane = t & 31, warp = t >> 5;
    const int m0 = blockIdx.y * 128, n0 = blockIdx.x * NCOLS;
    const int wm = (warp >> 1) * 64, wn = (warp & 1) * (NCOLS / 2);
    const int lrow = (lane & 7) + ((lane >> 3) & 1) * 8;
    const int lcol8 = (lane >> 4) * 8;

    auto issue = [&](int stg, int k0) {
        __nv_bfloat16* Ahs = smg + stg * STG;
        __nv_bfloat16* Als = Ahs + 128 * ASTR;
        __nv_bfloat16* Bhs = Als + 128 * ASTR;
        __nv_bfloat16* Bls = Bhs + 32 * BSTRX;
        #pragma unroll
        for (int i = 0; i < 4; i++) {                // A: 128x32, both planes
            int c = t + i * 128;
            int row = c >> 2, co = (c & 3) * 8;
            uint32_t da = row * ASTR + co;
            size_t sa = (size_t)(m0 + row) * K + k0 + co;
            CPA(sptr(Ahs + da), Ah + sa);
            CPA(sptr(Als + da), Al + sa);
        }
        #pragma unroll
        for (int i = 0; i < NCOLS / 32; i++) {       // B: 32xNCOLS, both planes
            int c = t + i * 128;
            int rb = c >> CSH, cb = (c & ((1 << CSH) - 1)) * 8;
            uint32_t db = rb * BSTRX + cb;
            size_t sb = (size_t)(k0 + rb) * N + n0 + cb;
            CPA(sptr(Bhs + db), Bh + sb);
            CPA(sptr(Bls + db), Bl + sb);
        }
    };

    float acc[4][NF][4] = {};
    const int KT = K / 32;
    issue(0, 0);  CPCOMMIT();
    issue(1, 32); CPCOMMIT();

    for (int kt = 0; kt < KT; kt++) {
        const int st = kt % 3;
        if (kt + 1 < KT) CPWAIT1(); else CPWAIT0();
        __syncthreads();
        if (kt + 2 < KT) { issue((kt + 2) % 3, (kt + 2) * 32); CPCOMMIT(); }

        const __nv_bfloat16* Ahb = smg + st * STG;
        const __nv_bfloat16* Alb = Ahb + 128 * ASTR;
        const __nv_bfloat16* Bhb = Alb + 128 * ASTR;
        const __nv_bfloat16* Blb = Bhb + 32 * BSTRX;

        #pragma unroll
        for (int ks = 0; ks < 2; ks++) {
            uint32_t ah[4][4], al[4][4];
            uint32_t bh[NF][2], bl[NF][2];
            #pragma unroll
            for (int mf = 0; mf < 4; mf++) {
                uint32_t ad = sptr(Ahb + (wm + mf * 16 + lrow) * ASTR + ks * 16 + lcol8);
                LDSM4(ah[mf][0], ah[mf][1], ah[mf][2], ah[mf][3], ad);
            }
            #pragma unroll
            for (int nf2 = 0; nf2 < NF / 2; nf2++) {
                uint32_t r0, r1, r2, r3;
                uint32_t bd = sptr(Bhb + (ks * 16 + lrow) * BSTRX + wn + nf2 * 16 + lcol8);
                LDSM4T(r0, r1, r2, r3, bd);
                bh[2 * nf2][0] = r0;     bh[2 * nf2][1] = r1;
                bh[2 * nf2 + 1][0] = r2; bh[2 * nf2 + 1][1] = r3;
            }
            #pragma unroll
            for (int mf = 0; mf < 4; mf++)          // hh
                #pragma unroll
                for (int nf = 0; nf < NF; nf++)
                    mma16816(acc[mf][nf], ah[mf], bh[nf][0], bh[nf][1]);
            #pragma unroll
            for (int mf = 0; mf < 4; mf++) {
                uint32_t ad = sptr(Alb + (wm + mf * 16 + lrow) * ASTR + ks * 16 + lcol8);
                LDSM4(al[mf][0], al[mf][1], al[mf][2], al[mf][3], ad);
            }
            #pragma unroll
            for (int mf = 0; mf < 4; mf++)          // lh
                #pragma unroll
                for (int nf = 0; nf < NF; nf++)
                    mma16816(acc[mf][nf], al[mf], bh[nf][0], bh[nf][1]);
            #pragma unroll
            for (int nf2 = 0; nf2 < NF / 2; nf2++) {
                uint32_t r0, r1, r2, r3;
                uint32_t bd = sptr(Blb + (ks * 16 + lrow) * BSTRX + wn + nf2 * 16 + lcol8);
                LDSM4T(r0, r1, r2, r3, bd);
                bl[2 * nf2][0] = r0;     bl[2 * nf2][1] = r1;
                bl[2 * nf2 + 1][0] = r2; bl[2 * nf2 + 1][1] = r3;
            }
            #pragma unroll
            for (int mf = 0; mf < 4; mf++)          // hl
                #pragma unroll
                for (int nf = 0; nf < NF; nf++)
                    mma16816(acc[mf][nf], ah[mf], bl[nf][0], bl[nf][1]);
        }
    }

    const int g = lane >> 2, tg = lane & 3;
    #pragma unroll
    for (int mf = 0; mf < 4; mf++) {
        #pragma unroll
        for (int nf = 0; nf < NF; nf++) {
            const int col = n0 + wn + nf * 8 + 2 * tg;
            #pragma unroll
            for (int half = 0; half < 2; half++) {
                const int row = m0 + wm + mf * 16 + g + half * 8;
                float vx = acc[mf][nf][half * 2], vy = acc[mf][nf][half * 2 + 1];
                if (MODE == 1) {
                    const int which = col / Hh;
                    const int rem = col - which * Hh;
                    const int head = rem >> 6, d0 = rem & 63;
                    const int bb = row >> 11, ss = row & (Ss - 1);
                    const size_t off =
                        ((((size_t)which * Bb + bb) * NH + head) * Ss + ss) * HD + d0;
                    if (which == 0) { vx *= SCL; vy *= SCL; }   // fold softmax scale into Q
                    uint32_t hi, lo;
                    split2(vx, vy, hi, lo);
                    *(uint32_t*)(g_qkvh + off) = hi;
                    *(uint32_t*)(g_qkvl + off) = lo;
                } else {
                    *(float2*)(C + (size_t)row * N + col) = make_float2(vx, vy);
                }
            }
        }
    }
}

#define GEMM_SMEM_128 (3 * (2 * 128 * ASTR + 2 * 32 * 136) * 2)
#define GEMM_SMEM_64  (3 * (2 * 128 * ASTR + 2 * 32 * 72) * 2)

// ---------------------------------------------------------------------------
// Flash attention (R12 baseline): 128 threads / 4 warps, warp 32 q x 64 kv,
// bf16x3, cp.async double-buffered, longest-first, SCL pre-folded into Q.
// ---------------------------------------------------------------------------
#define QSTR 72
#define ATTN_SMEM ((2 * 128 * QSTR + 8 * 64 * QSTR) * 2)  // bytes

__global__ void __launch_bounds__(128, 2)
attn_bf()
{
    extern __shared__ __align__(16) __nv_bfloat16 sma[];
    __nv_bfloat16* Qhi = sma;
    __nv_bfloat16* Qlo = Qhi + 128 * QSTR;
    __nv_bfloat16* Khs = Qlo + 128 * QSTR;
    __nv_bfloat16* Kls = Khs + 2 * 64 * QSTR;
    __nv_bfloat16* Vhs = Kls + 2 * 64 * QSTR;
    __nv_bfloat16* Vls = Vhs + 2 * 64 * QSTR;

    const int t = threadIdx.x;
    const int lane = t & 31, warp = t >> 5;
    const int iq = gridDim.x - 1 - blockIdx.x;   // longest CTAs first
    const int h = blockIdx.y, b = blockIdx.z;
    const int wm = warp * 32;
    const int g = lane >> 2, tg = lane & 3;
    const int lrow = (lane & 7) + ((lane >> 3) & 1) * 8;
    const int lcol8 = (lane >> 4) * 8;

    const size_t head_off = (((size_t)b * NH) + h) * (size_t)Ss * HD;
    const size_t plane = (size_t)Bb * NH * Ss * HD;
    const __nv_bfloat16* Qgh = g_qkvh + head_off + (size_t)iq * 128 * HD;
    const __nv_bfloat16* Qgl = g_qkvl + head_off + (size_t)iq * 128 * HD;
    const __nv_bfloat16* Kgh = g_qkvh + plane + head_off;
    const __nv_bfloat16* Kgl = g_qkvl + plane + head_off;
    const __nv_bfloat16* Vgh = g_qkvh + 2 * plane + head_off;
    const __nv_bfloat16* Vgl = g_qkvl + 2 * plane + head_off;

    auto issue_kv = [&](int jt, int stg) {
        #pragma unroll
        for (int i = 0; i < 4; i++) {
            int c = t + i * 128;
            int row = c >> 3, co = (c & 7) * 8;
            size_t src = (size_t)(jt * 64 + row) * HD + co;
            uint32_t doff = stg * 64 * QSTR + row * QSTR + co;
            CPA(sptr(Khs + doff), Kgh + src);
            CPA(sptr(Kls + doff), Kgl + src);
            CPA(sptr(Vhs + doff), Vgh + src);
            CPA(sptr(Vls + doff), Vgl + src);
        }
    };

    int st = 0;
    issue_kv(0, 0);
    CPCOMMIT();

    #pragma unroll
    for (int i = 0; i < 8; i++) {
        *(uint4*)(Qhi + t * QSTR + i * 8) = *(const uint4*)(Qgh + t * HD + i * 8);
        *(uint4*)(Qlo + t * QSTR + i * 8) = *(const uint4*)(Qgl + t * HD + i * 8);
    }

    float o[2][8][4] = {};
    float mi[4], li[4];
    #pragma unroll
    for (int i = 0; i < 4; i++) { mi[i] = -1e30f; li[i] = 0.f; }

    const int njt = 2 * iq + 2;
    for (int jt = 0; jt < njt; jt++) {
        if (jt + 1 < njt) { issue_kv(jt + 1, st ^ 1); CPCOMMIT(); CPWAIT1(); }
        else              { CPWAIT0(); }
        __syncthreads();

        const __nv_bfloat16* Khb = Khs + st * 64 * QSTR;
        const __nv_bfloat16* Klb = Kls + st * 64 * QSTR;
        const __nv_bfloat16* Vhb = Vhs + st * 64 * QSTR;
        const __nv_bfloat16* Vlb = Vls + st * 64 * QSTR;

        // ---- S = Q @ K^T: hh, lh, hl per ks ----
        float s[2][8][4] = {};
        #pragma unroll
        for (int ks = 0; ks < 4; ks++) {
            uint32_t qh[2][4], ql[2][4], kh[8][2], kl[8][2];
            #pragma unroll
            for (int mf = 0; mf < 2; mf++) {
                uint32_t ad = sptr(Qhi + (wm + mf * 16 + lrow) * QSTR + ks * 16 + lcol8);
                LDSM4(qh[mf][0], qh[mf][1], qh[mf][2], qh[mf][3], ad);
            }
            #pragma unroll
            for (int kf2 = 0; kf2 < 4; kf2++) {
                uint32_t r0, r1, r2, r3;
                uint32_t bd = sptr(Khb + (kf2 * 16 + (lane >> 4) * 8 + (lane & 7)) * QSTR +
                                   ks * 16 + ((lane >> 3) & 1) * 8);
                LDSM4(r0, r1, r2, r3, bd);
                kh[2 * kf2][0] = r0;     kh[2 * kf2][1] = r1;
                kh[2 * kf2 + 1][0] = r2; kh[2 * kf2 + 1][1] = r3;
            }
            #pragma unroll
            for (int mf = 0; mf < 2; mf++)
                #pragma unroll
                for (int nf = 0; nf < 8; nf++)
                    mma16816(s[mf][nf], qh[mf], kh[nf][0], kh[nf][1]);
            #pragma unroll
            for (int mf = 0; mf < 2; mf++) {
                uint32_t ad = sptr(Qlo + (wm + mf * 16 + lrow) * QSTR + ks * 16 + lcol8);
                LDSM4(ql[mf][0], ql[mf][1], ql[mf][2], ql[mf][3], ad);
            }
            #pragma unroll
            for (int mf = 0; mf < 2; mf++)
                #pragma unroll
                for (int nf = 0; nf < 8; nf++)
                    mma16816(s[mf][nf], ql[mf], kh[nf][0], kh[nf][1]);
            #pragma unroll
            for (int kf2 = 0; kf2 < 4; kf2++) {
                uint32_t r0, r1, r2, r3;
                uint32_t bd = sptr(Klb + (kf2 * 16 + (lane >> 4) * 8 + (lane & 7)) * QSTR +
                                   ks * 16 + ((lane >> 3) & 1) * 8);
                LDSM4(r0, r1, r2, r3, bd);
                kl[2 * kf2][0] = r0;     kl[2 * kf2][1] = r1;
                kl[2 * kf2 + 1][0] = r2; kl[2 * kf2 + 1][1] = r3;
            }
            #pragma unroll
            for (int mf = 0; mf < 2; mf++)
                #pragma unroll
                for (int nf = 0; nf < 8; nf++)
                    mma16816(s[mf][nf], qh[mf], kl[nf][0], kl[nf][1]);
        }

        // ---- mask, online softmax (scale pre-folded into Q) ----
        if (jt >= 2 * iq) {
            #pragma unroll
            for (int mf = 0; mf < 2; mf++)
                #pragma unroll
                for (int nf = 0; nf < 8; nf++)
                    #pragma unroll
                    for (int c = 0; c < 4; c++) {
                        int q = iq * 128 + wm + mf * 16 + g + (c >> 1) * 8;
                        int col = jt * 64 + nf * 8 + 2 * tg + (c & 1);
                        if (col > q) s[mf][nf][c] = -1e30f;
                    }
        }

        float fs[4];
        #pragma unroll
        for (int mf = 0; mf < 2; mf++) {
            #pragma unroll
            for (int half = 0; half < 2; half++) {
                const int ri = mf * 2 + half;
                float mt = -1e30f;
                #pragma unroll
                for (int nf = 0; nf < 8; nf++) {
                    mt = fmaxf(mt, s[mf][nf][half * 2]);
                    mt = fmaxf(mt, s[mf][nf][half * 2 + 1]);
                }
                mt = fmaxf(mt, __shfl_xor_sync(0xffffffffu, mt, 1));
                mt = fmaxf(mt, __shfl_xor_sync(0xffffffffu, mt, 2));
                float mn = fmaxf(mi[ri], mt);
                float f = exp2f(mi[ri] - mn);
                float rs = 0.f;
                #pragma unroll
                for (int nf = 0; nf < 8; nf++) {
                    float e0 = exp2f(s[mf][nf][half * 2] - mn);
                    float e1 = exp2f(s[mf][nf][half * 2 + 1] - mn);
                    s[mf][nf][half * 2] = e0;
                    s[mf][nf][half * 2 + 1] = e1;
                    rs += e0 + e1;
                }
                rs += __shfl_xor_sync(0xffffffffu, rs, 1);
                rs += __shfl_xor_sync(0xffffffffu, rs, 2);
                li[ri] = li[ri] * f + rs;
                mi[ri] = mn;
                fs[ri] = f;
            }
        }
        #pragma unroll
        for (int mf = 0; mf < 2; mf++)
            #pragma unroll
            for (int nf = 0; nf < 8; nf++)
                #pragma unroll
                for (int c = 0; c < 4; c++)
                    o[mf][nf][c] *= fs[mf * 2 + (c >> 1)];

        // ---- O += P @ V: PhVh, PlVh, PhVl per ks ----
        #pragma unroll
        for (int ks = 0; ks < 4; ks++) {
            uint32_t ph[2][4], pl[2][4], vh[8][2], vl[8][2];
            #pragma unroll
            for (int mf = 0; mf < 2; mf++) {
                const float* c0 = s[mf][2 * ks];
                const float* c1 = s[mf][2 * ks + 1];
                ph[mf][0] = packbf(c0[0], c0[1]);
                ph[mf][1] = packbf(c0[2], c0[3]);
                ph[mf][2] = packbf(c1[0], c1[1]);
                ph[mf][3] = packbf(c1[2], c1[3]);
                float2 hf;
                hf = unpackbf(ph[mf][0]); pl[mf][0] = packbf(c0[0] - hf.x, c0[1] - hf.y);
                hf = unpackbf(ph[mf][1]); pl[mf][1] = packbf(c0[2] - hf.x, c0[3] - hf.y);
                hf = unpackbf(ph[mf][2]); pl[mf][2] = packbf(c1[0] - hf.x, c1[1] - hf.y);
                hf = unpackbf(ph[mf][3]); pl[mf][3] = packbf(c1[2] - hf.x, c1[3] - hf.y);
            }
            #pragma unroll
            for (int df2 = 0; df2 < 4; df2++) {
                uint32_t r0, r1, r2, r3;
                uint32_t bd = sptr(Vhb + (ks * 16 + lrow) * QSTR + df2 * 16 + lcol8);
                LDSM4T(r0, r1, r2, r3, bd);
                vh[2 * df2][0] = r0;     vh[2 * df2][1] = r1;
                vh[2 * df2 + 1][0] = r2; vh[2 * df2 + 1][1] = r3;
            }
            #pragma unroll
            for (int mf = 0; mf < 2; mf++)
                #pragma unroll
                for (int nf = 0; nf < 8; nf++)
                    mma16816(o[mf][nf], ph[mf], vh[nf][0], vh[nf][1]);
            #pragma unroll
            for (int mf = 0; mf < 2; mf++)
                #pragma unroll
                for (int nf = 0; nf < 8; nf++)
                    mma16816(o[mf][nf], pl[mf], vh[nf][0], vh[nf][1]);
            #pragma unroll
            for (int df2 = 0; df2 < 4; df2++) {
                uint32_t r0, r1, r2, r3;
                uint32_t bd = sptr(Vlb + (ks * 16 + lrow) * QSTR + df2 * 16 + lcol8);
                LDSM4T(r0, r1, r2, r3, bd);
                vl[2 * df2][0] = r0;     vl[2 * df2][1] = r1;
                vl[2 * df2 + 1][0] = r2; vl[2 * df2 + 1][1] = r3;
            }
            #pragma unroll
            for (int mf = 0; mf < 2; mf++)
                #pragma unroll
                for (int nf = 0; nf < 8; nf++)
                    mma16816(o[mf][nf], ph[mf], vl[nf][0], vl[nf][1]);
        }
        __syncthreads();
        st ^= 1;
    }

    // epilogue: normalize, write ctx hi/lo bf16 [b][s][h*64+d]
    #pragma unroll
    for (int mf = 0; mf < 2; mf++) {
        #pragma unroll
        for (int half = 0; half < 2; half++) {
            const int ri = mf * 2 + half;
            const float inv = 1.0f / li[ri];
            const int row = iq * 128 + wm + mf * 16 + g + half * 8;
            #pragma unroll
            for (int nf = 0; nf < 8; nf++) {
                const int col = nf * 8 + 2 * tg;
                const size_t off = ((size_t)b * Ss + row) * Hh + h * HD + col;
                uint32_t hi, lo;
                split2(o[mf][nf][half * 2] * inv, o[mf][nf][half * 2 + 1] * inv,
                       hi, lo);
                *(uint32_t*)(g_ctxh + off) = hi;
                *(uint32_t*)(g_ctxl + off) = lo;
            }
        }
    }
}

// ---------------------------------------------------------------------------

extern "C" void kernel_launch(void* const* d_in, const int* in_sizes, int n_in,
                              void* d_out, int out_size)
{
    const float* x    = (const float*)d_in[0];   // [4,2048,768]
    const float* wqkv = (const float*)d_in[1];   // [768,2304]
    const float* wout = (const float*)d_in[2];   // [768,768]
    float* out = (float*)d_out;                  // [4,2048,768]

    __nv_bfloat16 *xh, *xl, *wqh, *wql, *woh, *wol, *ch, *cl;
    cudaGetSymbolAddress((void**)&xh,  g_xh);
    cudaGetSymbolAddress((void**)&xl,  g_xl);
    cudaGetSymbolAddress((void**)&wqh, g_wqh);
    cudaGetSymbolAddress((void**)&wql, g_wql);
    cudaGetSymbolAddress((void**)&woh, g_woh);
    cudaGetSymbolAddress((void**)&wol, g_wol);
    cudaGetSymbolAddress((void**)&ch,  g_ctxh);
    cudaGetSymbolAddress((void**)&cl,  g_ctxl);

    // 0) convert inputs to bf16 hi/lo
    cvt_kernel<<<(Bb * Ss * Hh / 4 + 255) / 256, 256>>>(x, xh, xl, Bb * Ss * Hh);
    cvt_kernel<<<(Hh * 3 * Hh / 4 + 255) / 256, 256>>>(wqkv, wqh, wql, Hh * 3 * Hh);
    cvt_kernel<<<(Hh * Hh / 4 + 255) / 256, 256>>>(wout, woh, wol, Hh * Hh);

    // 1) QKV projection, 128x128 tiles (scatter into g_qkvh/l, Q pre-scaled)
    cudaFuncSetAttribute((const void*)gemm_bf<1, 128>,
                         cudaFuncAttributeMaxDynamicSharedMemorySize, GEMM_SMEM_128);
    gemm_bf<1, 128><<<dim3(2304 / 128, 8192 / 128), 128, GEMM_SMEM_128>>>(
        xh, xl, wqh, wql, nullptr, Bb * Ss, 3 * Hh, Hh);

    // 2) Flash attention (causal), longest-first
    cudaFuncSetAttribute(attn_bf,
                         cudaFuncAttributeMaxDynamicSharedMemorySize, ATTN_SMEM);
    attn_bf<<<dim3(Ss / 128, NH, Bb), 128, ATTN_SMEM>>>();

    // 3) Output projection, 128x64 tiles (768 CTAs -> tail-free makespan)
    cudaFuncSetAttribute((const void*)gemm_bf<2, 64>,
                         cudaFuncAttributeMaxDynamicSharedMemorySize, GEMM_SMEM_64);
    gemm_bf<2, 64><<<dim3(768 / 64, 8192 / 128), 128, GEMM_SMEM_64>>>(
        ch, cl, woh, wol, out, Bb * Ss, Hh, Hh);
}

// round 15
// speedup vs baseline: 1.5985x; 1.5985x over previous
#include <cuda_runtime.h>
#include <cuda_bf16.h>
#include <stdint.h>
#include <math.h>

#define Bb 4
#define Ss 2048
#define Hh 768
#define NH 12
#define HD 64

// ---------------------------------------------------------------------------
// Scratch (allocation-free rule: __device__ globals) — bf16 hi/lo planes
// ---------------------------------------------------------------------------
__device__ __nv_bfloat16 g_xh[Bb * Ss * Hh],  g_xl[Bb * Ss * Hh];
__device__ __nv_bfloat16 g_wqh[Hh * 3 * Hh],  g_wql[Hh * 3 * Hh];
__device__ __nv_bfloat16 g_woh[Hh * Hh],      g_wol[Hh * Hh];
__device__ __nv_bfloat16 g_qkvh[3 * Bb * NH * Ss * HD], g_qkvl[3 * Bb * NH * Ss * HD];
__device__ __nv_bfloat16 g_ctxh[Bb * Ss * Hh], g_ctxl[Bb * Ss * Hh];

#define SCL 0.18033688011112042f   // 0.125 * log2(e), folded into Q at QKV epilogue

// ---------------------------------------------------------------------------
// Helpers
// ---------------------------------------------------------------------------
__device__ __forceinline__ uint32_t packbf(float lo, float hi) {
    uint32_t r;
    asm("cvt.rn.bf16x2.f32 %0, %1, %2;" : "=r"(r) : "f"(hi), "f"(lo));
    return r;
}
__device__ __forceinline__ float2 unpackbf(uint32_t u) {
    __nv_bfloat162 h = *reinterpret_cast<__nv_bfloat162*>(&u);
    return make_float2(__bfloat162float(h.x), __bfloat162float(h.y));
}
__device__ __forceinline__ void split2(float x, float y, uint32_t& hi, uint32_t& lo) {
    hi = packbf(x, y);
    float2 h = unpackbf(hi);
    lo = packbf(x - h.x, y - h.y);
}

#define LDSM4(r0, r1, r2, r3, a)                                              \
    asm volatile("ldmatrix.sync.aligned.m8n8.x4.shared.b16 {%0,%1,%2,%3}, [%4];" \
                 : "=r"(r0), "=r"(r1), "=r"(r2), "=r"(r3) : "r"(a))
#define LDSM4T(r0, r1, r2, r3, a)                                             \
    asm volatile("ldmatrix.sync.aligned.m8n8.x4.trans.shared.b16 {%0,%1,%2,%3}, [%4];" \
                 : "=r"(r0), "=r"(r1), "=r"(r2), "=r"(r3) : "r"(a))
#define CPA(dst, src)                                                         \
    asm volatile("cp.async.cg.shared.global [%0], [%1], 16;" :: "r"(dst), "l"(src))
#define CPCOMMIT() asm volatile("cp.async.commit_group;")
#define CPWAIT0()  asm volatile("cp.async.wait_group 0;")
#define CPWAIT1()  asm volatile("cp.async.wait_group 1;")

__device__ __forceinline__ void mma16816(float* c, const uint32_t* a,
                                         uint32_t b0, uint32_t b1) {
    asm volatile(
        "mma.sync.aligned.m16n8k16.row.col.f32.bf16.bf16.f32 "
        "{%0,%1,%2,%3}, {%4,%5,%6,%7}, {%8,%9}, {%0,%1,%2,%3};"
        : "+f"(c[0]), "+f"(c[1]), "+f"(c[2]), "+f"(c[3])
        : "r"(a[0]), "r"(a[1]), "r"(a[2]), "r"(a[3]), "r"(b0), "r"(b1));
}
__device__ __forceinline__ uint32_t sptr(const void* p) {
    return (uint32_t)__cvta_generic_to_shared(p);
}

// ---------------------------------------------------------------------------
// fp32 -> bf16 hi/lo convert prepass
// ---------------------------------------------------------------------------
__global__ void cvt_kernel(const float* __restrict__ in,
                           __nv_bfloat16* __restrict__ hi,
                           __nv_bfloat16* __restrict__ lo, int n)
{
    int i = (blockIdx.x * blockDim.x + threadIdx.x) * 4;
    if (i < n) {
        float4 v = *(const float4*)(in + i);
        uint32_t h0, l0, h1, l1;
        split2(v.x, v.y, h0, l0);
        split2(v.z, v.w, h1, l1);
        uint32_t* ph = (uint32_t*)(hi + i);
        uint32_t* pl = (uint32_t*)(lo + i);
        ph[0] = h0; ph[1] = h1;
        pl[0] = l0; pl[1] = l1;
    }
}

// ---------------------------------------------------------------------------
// Projection GEMM (R12 champion): bf16x3, 128x128 CTA tile, BK=32,
// 4 warps of 64x64, 3-stage cp.async, single barrier per k-chunk.
// MODE 1: scatter epilogue -> g_qkvh/l (Q scaled by SCL). MODE 2: fp32 C.
// ---------------------------------------------------------------------------
#define ASTR 40
#define BSTR 136
#define STAGE_H (2 * 128 * ASTR + 2 * 32 * BSTR)
#define GEMM_SMEM (3 * STAGE_H * 2)

template <int MODE>
__global__ void __launch_bounds__(128, 2)
gemm_bf(const __nv_bfloat16* __restrict__ Ah, const __nv_bfloat16* __restrict__ Al,
        const __nv_bfloat16* __restrict__ Bh, const __nv_bfloat16* __restrict__ Bl,
        float* __restrict__ C, int M, int N, int K)
{
    extern __shared__ __align__(16) __nv_bfloat16 smg[];

    const int t = threadIdx.x;
    const int lane = t & 31, warp = t >> 5;
    const int m0 = blockIdx.y * 128, n0 = blockIdx.x * 128;
    const int wm = (warp >> 1) * 64, wn = (warp & 1) * 64;
    const int lrow = (lane & 7) + ((lane >> 3) & 1) * 8;
    const int lcol8 = (lane >> 4) * 8;

    auto issue = [&](int stg, int k0) {
        __nv_bfloat16* Ahs = smg + stg * STAGE_H;
        __nv_bfloat16* Als = Ahs + 128 * ASTR;
        __nv_bfloat16* Bhs = Als + 128 * ASTR;
        __nv_bfloat16* Bls = Bhs + 32 * BSTR;
        #pragma unroll
        for (int i = 0; i < 4; i++) {
            int c = t + i * 128;                  // 0..511
            int row = c >> 2, co = (c & 3) * 8;
            uint32_t da = row * ASTR + co;
            size_t sa = (size_t)(m0 + row) * K + k0 + co;
            CPA(sptr(Ahs + da), Ah + sa);
            CPA(sptr(Als + da), Al + sa);
            int rb = c >> 4, cb = (c & 15) * 8;
            uint32_t db = rb * BSTR + cb;
            size_t sb = (size_t)(k0 + rb) * N + n0 + cb;
            CPA(sptr(Bhs + db), Bh + sb);
            CPA(sptr(Bls + db), Bl + sb);
        }
    };

    float acc[4][8][4] = {};
    const int KT = K / 32;
    issue(0, 0);  CPCOMMIT();
    issue(1, 32); CPCOMMIT();

    for (int kt = 0; kt < KT; kt++) {
        const int st = kt % 3;
        if (kt + 1 < KT) CPWAIT1(); else CPWAIT0();
        __syncthreads();
        if (kt + 2 < KT) { issue((kt + 2) % 3, (kt + 2) * 32); CPCOMMIT(); }

        const __nv_bfloat16* Ahb = smg + st * STAGE_H;
        const __nv_bfloat16* Alb = Ahb + 128 * ASTR;
        const __nv_bfloat16* Bhb = Alb + 128 * ASTR;
        const __nv_bfloat16* Blb = Bhb + 32 * BSTR;

        #pragma unroll
        for (int ks = 0; ks < 2; ks++) {
            uint32_t ah[4][4], al[4][4];
            uint32_t bh[8][2], bl[8][2];
            #pragma unroll
            for (int mf = 0; mf < 4; mf++) {
                uint32_t ad = sptr(Ahb + (wm + mf * 16 + lrow) * ASTR + ks * 16 + lcol8);
                LDSM4(ah[mf][0], ah[mf][1], ah[mf][2], ah[mf][3], ad);
            }
            #pragma unroll
            for (int nf2 = 0; nf2 < 4; nf2++) {
                uint32_t r0, r1, r2, r3;
                uint32_t bd = sptr(Bhb + (ks * 16 + lrow) * BSTR + wn + nf2 * 16 + lcol8);
                LDSM4T(r0, r1, r2, r3, bd);
                bh[2 * nf2][0] = r0;     bh[2 * nf2][1] = r1;
                bh[2 * nf2 + 1][0] = r2; bh[2 * nf2 + 1][1] = r3;
            }
            #pragma unroll
            for (int mf = 0; mf < 4; mf++)          // hh
                #pragma unroll
                for (int nf = 0; nf < 8; nf++)
                    mma16816(acc[mf][nf], ah[mf], bh[nf][0], bh[nf][1]);
            #pragma unroll
            for (int mf = 0; mf < 4; mf++) {
                uint32_t ad = sptr(Alb + (wm + mf * 16 + lrow) * ASTR + ks * 16 + lcol8);
                LDSM4(al[mf][0], al[mf][1], al[mf][2], al[mf][3], ad);
            }
            #pragma unroll
            for (int mf = 0; mf < 4; mf++)          // lh
                #pragma unroll
                for (int nf = 0; nf < 8; nf++)
                    mma16816(acc[mf][nf], al[mf], bh[nf][0], bh[nf][1]);
            #pragma unroll
            for (int nf2 = 0; nf2 < 4; nf2++) {
                uint32_t r0, r1, r2, r3;
                uint32_t bd = sptr(Blb + (ks * 16 + lrow) * BSTR + wn + nf2 * 16 + lcol8);
                LDSM4T(r0, r1, r2, r3, bd);
                bl[2 * nf2][0] = r0;     bl[2 * nf2][1] = r1;
                bl[2 * nf2 + 1][0] = r2; bl[2 * nf2 + 1][1] = r3;
            }
            #pragma unroll
            for (int mf = 0; mf < 4; mf++)          // hl
                #pragma unroll
                for (int nf = 0; nf < 8; nf++)
                    mma16816(acc[mf][nf], ah[mf], bl[nf][0], bl[nf][1]);
        }
    }

    const int g = lane >> 2, tg = lane & 3;
    #pragma unroll
    for (int mf = 0; mf < 4; mf++) {
        #pragma unroll
        for (int nf = 0; nf < 8; nf++) {
            const int col = n0 + wn + nf * 8 + 2 * tg;
            #pragma unroll
            for (int half = 0; half < 2; half++) {
                const int row = m0 + wm + mf * 16 + g + half * 8;
                float vx = acc[mf][nf][half * 2], vy = acc[mf][nf][half * 2 + 1];
                if (MODE == 1) {
                    const int which = col / Hh;
                    const int rem = col - which * Hh;
                    const int head = rem >> 6, d0 = rem & 63;
                    const int bb = row >> 11, ss = row & (Ss - 1);
                    const size_t off =
                        ((((size_t)which * Bb + bb) * NH + head) * Ss + ss) * HD + d0;
                    if (which == 0) { vx *= SCL; vy *= SCL; }   // fold softmax scale into Q
                    uint32_t hi, lo;
                    split2(vx, vy, hi, lo);
                    *(uint32_t*)(g_qkvh + off) = hi;
                    *(uint32_t*)(g_qkvl + off) = lo;
                } else {
                    *(float2*)(C + (size_t)row * N + col) = make_float2(vx, vy);
                }
            }
        }
    }
}

// ---------------------------------------------------------------------------
// Flash attention (R12 champion): 128 threads / 4 warps, warp 32 q x 64 kv,
// bf16x3, cp.async double-buffered, longest-first, SCL pre-folded into Q.
// ---------------------------------------------------------------------------
#define QSTR 72
#define ATTN_SMEM ((2 * 128 * QSTR + 8 * 64 * QSTR) * 2)  // bytes

__global__ void __launch_bounds__(128, 2)
attn_bf()
{
    extern __shared__ __align__(16) __nv_bfloat16 sma[];
    __nv_bfloat16* Qhi = sma;
    __nv_bfloat16* Qlo = Qhi + 128 * QSTR;
    __nv_bfloat16* Khs = Qlo + 128 * QSTR;
    __nv_bfloat16* Kls = Khs + 2 * 64 * QSTR;
    __nv_bfloat16* Vhs = Kls + 2 * 64 * QSTR;
    __nv_bfloat16* Vls = Vhs + 2 * 64 * QSTR;

    const int t = threadIdx.x;
    const int lane = t & 31, warp = t >> 5;
    const int iq = gridDim.x - 1 - blockIdx.x;   // longest CTAs first
    const int h = blockIdx.y, b = blockIdx.z;
    const int wm = warp * 32;
    const int g = lane >> 2, tg = lane & 3;
    const int lrow = (lane & 7) + ((lane >> 3) & 1) * 8;
    const int lcol8 = (lane >> 4) * 8;

    const size_t head_off = (((size_t)b * NH) + h) * (size_t)Ss * HD;
    const size_t plane = (size_t)Bb * NH * Ss * HD;
    const __nv_bfloat16* Qgh = g_qkvh + head_off + (size_t)iq * 128 * HD;
    const __nv_bfloat16* Qgl = g_qkvl + head_off + (size_t)iq * 128 * HD;
    const __nv_bfloat16* Kgh = g_qkvh + plane + head_off;
    const __nv_bfloat16* Kgl = g_qkvl + plane + head_off;
    const __nv_bfloat16* Vgh = g_qkvh + 2 * plane + head_off;
    const __nv_bfloat16* Vgl = g_qkvl + 2 * plane + head_off;

    auto issue_kv = [&](int jt, int stg) {
        #pragma unroll
        for (int i = 0; i < 4; i++) {
            int c = t + i * 128;
            int row = c >> 3, co = (c & 7) * 8;
            size_t src = (size_t)(jt * 64 + row) * HD + co;
            uint32_t doff = stg * 64 * QSTR + row * QSTR + co;
            CPA(sptr(Khs + doff), Kgh + src);
            CPA(sptr(Kls + doff), Kgl + src);
            CPA(sptr(Vhs + doff), Vgh + src);
            CPA(sptr(Vls + doff), Vgl + src);
        }
    };

    int st = 0;
    issue_kv(0, 0);
    CPCOMMIT();

    #pragma unroll
    for (int i = 0; i < 8; i++) {
        *(uint4*)(Qhi + t * QSTR + i * 8) = *(const uint4*)(Qgh + t * HD + i * 8);
        *(uint4*)(Qlo + t * QSTR + i * 8) = *(const uint4*)(Qgl + t * HD + i * 8);
    }

    float o[2][8][4] = {};
    float mi[4], li[4];
    #pragma unroll
    for (int i = 0; i < 4; i++) { mi[i] = -1e30f; li[i] = 0.f; }

    const int njt = 2 * iq + 2;
    for (int jt = 0; jt < njt; jt++) {
        if (jt + 1 < njt) { issue_kv(jt + 1, st ^ 1); CPCOMMIT(); CPWAIT1(); }
        else              { CPWAIT0(); }
        __syncthreads();

        const __nv_bfloat16* Khb = Khs + st * 64 * QSTR;
        const __nv_bfloat16* Klb = Kls + st * 64 * QSTR;
        const __nv_bfloat16* Vhb = Vhs + st * 64 * QSTR;
        const __nv_bfloat16* Vlb = Vls + st * 64 * QSTR;

        // ---- S = Q @ K^T: hh, lh, hl per ks ----
        float s[2][8][4] = {};
        #pragma unroll
        for (int ks = 0; ks < 4; ks++) {
            uint32_t qh[2][4], ql[2][4], kh[8][2], kl[8][2];
            #pragma unroll
            for (int mf = 0; mf < 2; mf++) {
                uint32_t ad = sptr(Qhi + (wm + mf * 16 + lrow) * QSTR + ks * 16 + lcol8);
                LDSM4(qh[mf][0], qh[mf][1], qh[mf][2], qh[mf][3], ad);
            }
            #pragma unroll
            for (int kf2 = 0; kf2 < 4; kf2++) {
                uint32_t r0, r1, r2, r3;
                uint32_t bd = sptr(Khb + (kf2 * 16 + (lane >> 4) * 8 + (lane & 7)) * QSTR +
                                   ks * 16 + ((lane >> 3) & 1) * 8);
                LDSM4(r0, r1, r2, r3, bd);
                kh[2 * kf2][0] = r0;     kh[2 * kf2][1] = r1;
                kh[2 * kf2 + 1][0] = r2; kh[2 * kf2 + 1][1] = r3;
            }
            #pragma unroll
            for (int mf = 0; mf < 2; mf++)
                #pragma unroll
                for (int nf = 0; nf < 8; nf++)
                    mma16816(s[mf][nf], qh[mf], kh[nf][0], kh[nf][1]);
            #pragma unroll
            for (int mf = 0; mf < 2; mf++) {
                uint32_t ad = sptr(Qlo + (wm + mf * 16 + lrow) * QSTR + ks * 16 + lcol8);
                LDSM4(ql[mf][0], ql[mf][1], ql[mf][2], ql[mf][3], ad);
            }
            #pragma unroll
            for (int mf = 0; mf < 2; mf++)
                #pragma unroll
                for (int nf = 0; nf < 8; nf++)
                    mma16816(s[mf][nf], ql[mf], kh[nf][0], kh[nf][1]);
            #pragma unroll
            for (int kf2 = 0; kf2 < 4; kf2++) {
                uint32_t r0, r1, r2, r3;
                uint32_t bd = sptr(Klb + (kf2 * 16 + (lane >> 4) * 8 + (lane & 7)) * QSTR +
                                   ks * 16 + ((lane >> 3) & 1) * 8);
                LDSM4(r0, r1, r2, r3, bd);
                kl[2 * kf2][0] = r0;     kl[2 * kf2][1] = r1;
                kl[2 * kf2 + 1][0] = r2; kl[2 * kf2 + 1][1] = r3;
            }
            #pragma unroll
            for (int mf = 0; mf < 2; mf++)
                #pragma unroll
                for (int nf = 0; nf < 8; nf++)
                    mma16816(s[mf][nf], qh[mf], kl[nf][0], kl[nf][1]);
        }

        // ---- mask, online softmax (scale pre-folded into Q) ----
        if (jt >= 2 * iq) {
            #pragma unroll
            for (int mf = 0; mf < 2; mf++)
                #pragma unroll
                for (int nf = 0; nf < 8; nf++)
                    #pragma unroll
                    for (int c = 0; c < 4; c++) {
                        int q = iq * 128 + wm + mf * 16 + g + (c >> 1) * 8;
                        int col = jt * 64 + nf * 8 + 2 * tg + (c & 1);
                        if (col > q) s[mf][nf][c] = -1e30f;
                    }
        }

        float fs[4];
        #pragma unroll
        for (int mf = 0; mf < 2; mf++) {
            #pragma unroll
            for (int half = 0; half < 2; half++) {
                const int ri = mf * 2 + half;
                float mt = -1e30f;
                #pragma unroll
                for (int nf = 0; nf < 8; nf++) {
                    mt = fmaxf(mt, s[mf][nf][half * 2]);
                    mt = fmaxf(mt, s[mf][nf][half * 2 + 1]);
                }
                mt = fmaxf(mt, __shfl_xor_sync(0xffffffffu, mt, 1));
                mt = fmaxf(mt, __shfl_xor_sync(0xffffffffu, mt, 2));
                float mn = fmaxf(mi[ri], mt);
                float f = exp2f(mi[ri] - mn);
                float rs = 0.f;
                #pragma unroll
                for (int nf = 0; nf < 8; nf++) {
                    float e0 = exp2f(s[mf][nf][half * 2] - mn);
                    float e1 = exp2f(s[mf][nf][half * 2 + 1] - mn);
                    s[mf][nf][half * 2] = e0;
                    s[mf][nf][half * 2 + 1] = e1;
                    rs += e0 + e1;
                }
                rs += __shfl_xor_sync(0xffffffffu, rs, 1);
                rs += __shfl_xor_sync(0xffffffffu, rs, 2);
                li[ri] = li[ri] * f + rs;
                mi[ri] = mn;
                fs[ri] = f;
            }
        }
        #pragma unroll
        for (int mf = 0; mf < 2; mf++)
            #pragma unroll
            for (int nf = 0; nf < 8; nf++)
                #pragma unroll
                for (int c = 0; c < 4; c++)
                    o[mf][nf][c] *= fs[mf * 2 + (c >> 1)];

        // ---- O += P @ V: PhVh, PlVh, PhVl per ks ----
        #pragma unroll
        for (int ks = 0; ks < 4; ks++) {
            uint32_t ph[2][4], pl[2][4], vh[8][2], vl[8][2];
            #pragma unroll
            for (int mf = 0; mf < 2; mf++) {
                const float* c0 = s[mf][2 * ks];
                const float* c1 = s[mf][2 * ks + 1];
                ph[mf][0] = packbf(c0[0], c0[1]);
                ph[mf][1] = packbf(c0[2], c0[3]);
                ph[mf][2] = packbf(c1[0], c1[1]);
                ph[mf][3] = packbf(c1[2], c1[3]);
                float2 hf;
                hf = unpackbf(ph[mf][0]); pl[mf][0] = packbf(c0[0] - hf.x, c0[1] - hf.y);
                hf = unpackbf(ph[mf][1]); pl[mf][1] = packbf(c0[2] - hf.x, c0[3] - hf.y);
                hf = unpackbf(ph[mf][2]); pl[mf][2] = packbf(c1[0] - hf.x, c1[1] - hf.y);
                hf = unpackbf(ph[mf][3]); pl[mf][3] = packbf(c1[2] - hf.x, c1[3] - hf.y);
            }
            #pragma unroll
            for (int df2 = 0; df2 < 4; df2++) {
                uint32_t r0, r1, r2, r3;
                uint32_t bd = sptr(Vhb + (ks * 16 + lrow) * QSTR + df2 * 16 + lcol8);
                LDSM4T(r0, r1, r2, r3, bd);
                vh[2 * df2][0] = r0;     vh[2 * df2][1] = r1;
                vh[2 * df2 + 1][0] = r2; vh[2 * df2 + 1][1] = r3;
            }
            #pragma unroll
            for (int mf = 0; mf < 2; mf++)
                #pragma unroll
                for (int nf = 0; nf < 8; nf++)
                    mma16816(o[mf][nf], ph[mf], vh[nf][0], vh[nf][1]);
            #pragma unroll
            for (int mf = 0; mf < 2; mf++)
                #pragma unroll
                for (int nf = 0; nf < 8; nf++)
                    mma16816(o[mf][nf], pl[mf], vh[nf][0], vh[nf][1]);
            #pragma unroll
            for (int df2 = 0; df2 < 4; df2++) {
                uint32_t r0, r1, r2, r3;
                uint32_t bd = sptr(Vlb + (ks * 16 + lrow) * QSTR + df2 * 16 + lcol8);
                LDSM4T(r0, r1, r2, r3, bd);
                vl[2 * df2][0] = r0;     vl[2 * df2][1] = r1;
                vl[2 * df2 + 1][0] = r2; vl[2 * df2 + 1][1] = r3;
            }
            #pragma unroll
            for (int mf = 0; mf < 2; mf++)
                #pragma unroll
                for (int nf = 0; nf < 8; nf++)
                    mma16816(o[mf][nf], ph[mf], vl[nf][0], vl[nf][1]);
        }
        __syncthreads();
        st ^= 1;
    }

    // epilogue: normalize, write ctx hi/lo bf16 [b][s][h*64+d]
    #pragma unroll
    for (int mf = 0; mf < 2; mf++) {
        #pragma unroll
        for (int half = 0; half < 2; half++) {
            const int ri = mf * 2 + half;
            const float inv = 1.0f / li[ri];
            const int row = iq * 128 + wm + mf * 16 + g + half * 8;
            #pragma unroll
            for (int nf = 0; nf < 8; nf++) {
                const int col = nf * 8 + 2 * tg;
                const size_t off = ((size_t)b * Ss + row) * Hh + h * HD + col;
                uint32_t hi, lo;
                split2(o[mf][nf][half * 2] * inv, o[mf][nf][half * 2 + 1] * inv,
                       hi, lo);
                *(uint32_t*)(g_ctxh + off) = hi;
                *(uint32_t*)(g_ctxl + off) = lo;
            }
        }
    }
}

// ---------------------------------------------------------------------------

extern "C" void kernel_launch(void* const* d_in, const int* in_sizes, int n_in,
                              void* d_out, int out_size)
{
    const float* x    = (const float*)d_in[0];   // [4,2048,768]
    const float* wqkv = (const float*)d_in[1];   // [768,2304]
    const float* wout = (const float*)d_in[2];   // [768,768]
    float* out = (float*)d_out;                  // [4,2048,768]

    __nv_bfloat16 *xh, *xl, *wqh, *wql, *woh, *wol, *ch, *cl;
    cudaGetSymbolAddress((void**)&xh,  g_xh);
    cudaGetSymbolAddress((void**)&xl,  g_xl);
    cudaGetSymbolAddress((void**)&wqh, g_wqh);
    cudaGetSymbolAddress((void**)&wql, g_wql);
    cudaGetSymbolAddress((void**)&woh, g_woh);
    cudaGetSymbolAddress((void**)&wol, g_wol);
    cudaGetSymbolAddress((void**)&ch,  g_ctxh);
    cudaGetSymbolAddress((void**)&cl,  g_ctxl);

    // 0) convert inputs to bf16 hi/lo
    cvt_kernel<<<(Bb * Ss * Hh / 4 + 255) / 256, 256>>>(x, xh, xl, Bb * Ss * Hh);
    cvt_kernel<<<(Hh * 3 * Hh / 4 + 255) / 256, 256>>>(wqkv, wqh, wql, Hh * 3 * Hh);
    cvt_kernel<<<(Hh * Hh / 4 + 255) / 256, 256>>>(wout, woh, wol, Hh * Hh);

    // 1) QKV projection (scatter into g_qkvh/l, Q pre-scaled)
    cudaFuncSetAttribute(gemm_bf<1>,
                         cudaFuncAttributeMaxDynamicSharedMemorySize, GEMM_SMEM);
    gemm_bf<1><<<dim3(2304 / 128, 8192 / 128), 128, GEMM_SMEM>>>(
        xh, xl, wqh, wql, nullptr, Bb * Ss, 3 * Hh, Hh);

    // 2) Flash attention (causal), longest-first
    cudaFuncSetAttribute(attn_bf,
                         cudaFuncAttributeMaxDynamicSharedMemorySize, ATTN_SMEM);
    attn_bf<<<dim3(Ss / 128, NH, Bb), 128, ATTN_SMEM>>>();

    // 3) Output projection
    cudaFuncSetAttribute(gemm_bf<2>,
                         cudaFuncAttributeMaxDynamicSharedMemorySize, GEMM_SMEM);
    gemm_bf<2><<<dim3(768 / 128, 8192 / 128), 128, GEMM_SMEM>>>(
        ch, cl, woh, wol, out, Bb * Ss, Hh, Hh);
}